// round 12
// baseline (speedup 1.0000x reference)
#include <cuda_runtime.h>
#include <math.h>

#define BB 2
#define NN 4096
#define NODES (BB*NN)
#define KK 32
#define D0 64
#define D1 16
#define D13 48
#define RH 16
#define EPSF 1e-6f
#define SCALE 0.1889822365046136f

typedef unsigned long long u64;

__device__ float s_f0[NODES*D0];
__device__ float s_f1[NODES*D13];
__device__ float s_g0[NODES*D0];
__device__ float s_g1[NODES*D13];
__device__ float s_q0[NODES*D0];
__device__ float s_q1[NODES*D13];

__device__ __forceinline__ float gelu_f(float x){
    float x3 = x*x*x;
    return 0.5f*x*(1.0f + tanhf(0.7978845608028654f*(x + 0.044715f*x3)));
}
__device__ __forceinline__ u64 pk2(float lo, float hi){
    u64 r; asm("mov.b64 %0,{%1,%2};" : "=l"(r) : "f"(lo), "f"(hi)); return r;
}
__device__ __forceinline__ u64 dup2(float x){ return pk2(x,x); }
__device__ __forceinline__ void upk2(float&lo, float&hi, u64 v){
    asm("mov.b64 {%0,%1},%2;" : "=f"(lo), "=f"(hi) : "l"(v));
}
__device__ __forceinline__ void fma2(u64 &d, u64 a, u64 b){
    asm("fma.rn.f32x2 %0,%1,%2,%0;" : "+l"(d) : "l"(a), "l"(b));
}
__device__ __forceinline__ float wred(float v){
    #pragma unroll
    for(int o=16;o>0;o>>=1) v += __shfl_xor_sync(0xffffffffu, v, o);
    return v;
}

__global__ void init_kernel(const float* __restrict__ f0, const float* __restrict__ f1){
    int i = blockIdx.x*blockDim.x + threadIdx.x;
    if(i < NODES*D0)  s_f0[i] = f0[i];
    if(i < NODES*D13) s_f1[i] = f1[i];
}

// ---------------- prenorm + Q (warp per node) ----------------
__global__ void __launch_bounds__(256) prenorm_q_kernel(
    const float* __restrict__ Wq0, const float* __restrict__ Wq1)
{
    __shared__ float Wq0s[D0*D0];
    __shared__ float Wq1s[D1*D1];
    __shared__ float g1tmp[8][49];
    int t = threadIdx.x, w = t>>5, lane = t&31;
    for(int i=t;i<D0*D0;i+=256) Wq0s[i]=Wq0[i];
    for(int i=t;i<D1*D1;i+=256) Wq1s[i]=Wq1[i];
    __syncthreads();
    int nd = blockIdx.x*8 + w;
    if(nd >= NODES) return;
    float x0 = s_f0[nd*D0+lane], x1 = s_f0[nd*D0+32+lane];
    float mean = wred(x0+x1)*(1.0f/64.0f);
    float d0_ = x0-mean, d1_ = x1-mean;
    float var = wred(d0_*d0_ + d1_*d1_)*(1.0f/64.0f);
    float rs = rsqrtf(var+EPSF);
    float g0a = d0_*rs, g0b = d1_*rs;
    s_g0[nd*D0+lane]=g0a; s_g0[nd*D0+32+lane]=g0b;
    float y0 = s_f1[nd*D13+lane];
    float y1 = (lane<16)? s_f1[nd*D13+32+lane] : 0.0f;
    float rms = rsqrtf(wred(y0*y0+y1*y1)*(1.0f/16.0f)+EPSF);
    float g1a = y0*rms, g1b = y1*rms;
    s_g1[nd*D13+lane]=g1a;
    if(lane<16) s_g1[nd*D13+32+lane]=g1b;
    g1tmp[w][lane]=g1a;
    if(lane<16) g1tmp[w][32+lane]=g1b;
    __syncwarp();
    u64 acc = 0;
    #pragma unroll 8
    for(int c=0;c<D0;c++){
        float xc = (c<32)? __shfl_sync(0xffffffffu,g0a,c) : __shfl_sync(0xffffffffu,g0b,c-32);
        u64 wp = *reinterpret_cast<const u64*>(&Wq0s[c*D0 + 2*lane]);
        fma2(acc, dup2(xc), wp);
    }
    float qlo,qhi; upk2(qlo,qhi,acc);
    s_q0[nd*D0+2*lane]=qlo; s_q0[nd*D0+2*lane+1]=qhi;
    if(lane<16){
        float a0=0.f,a1=0.f,a2=0.f;
        #pragma unroll
        for(int c=0;c<D1;c++){
            float wv = Wq1s[c*D1+lane];
            a0 += g1tmp[w][c*3+0]*wv;
            a1 += g1tmp[w][c*3+1]*wv;
            a2 += g1tmp[w][c*3+2]*wv;
        }
        s_q1[nd*D13+lane*3+0]=a0;
        s_q1[nd*D13+lane*3+1]=a1;
        s_q1[nd*D13+lane*3+2]=a2;
    }
}

// ---------------- attention: 4 nodes per 512-thread CTA ----------------
struct AttnSmem {
    float Wk00[4096], Wv00[4096], Wo0[4096];
    float Wk10[1024], Wv10[1024], Rw20[1024];
    float Wk01t[1024], Wv01t[1024];                    // transposed [ec][64]
    float Wk11t[256], Wk11rt[256], Wv11t[256], Wv11rt[256], Rw21t[256]; // [ec][16]
    float Wo1[256];
    float Rw1[16], Rb1[16];
    float v0s[4][KK*D0];
    float v1s[4][KK*D13];
    float h0g[4][4][8][66];
    float h1g[4][4][8][48];    // planar: [m*16+c]
    float dot1g[4][4][8][16];
    float rhg[4][4][8][16];
    float rh4[4][4][8][4];
    float logits[4][4][33];
    float a_s[4][4][33];
    float q0s[4][D0], q1s[4][D13], o0s[4][D0], o1s[4][D13];
    float ci[4][4];
};

__global__ void __launch_bounds__(512) attn_kernel(
    const float* __restrict__ coords, const int* __restrict__ nbr,
    const float* __restrict__ gWk00, const float* __restrict__ gWk10,
    const float* __restrict__ gWk01, const float* __restrict__ gWk11,
    const float* __restrict__ gWk11r,
    const float* __restrict__ gWv00, const float* __restrict__ gWv10,
    const float* __restrict__ gWv01, const float* __restrict__ gWv11,
    const float* __restrict__ gWv11r,
    const float* __restrict__ gRw1, const float* __restrict__ gRb1,
    const float* __restrict__ gRw20, const float* __restrict__ gRw21,
    const float* __restrict__ gWo0, const float* __restrict__ gWo1)
{
    extern __shared__ float smem_raw[];
    AttnSmem& S = *reinterpret_cast<AttnSmem*>(smem_raw);
    int t = threadIdx.x, slot = t>>7, tt = t&127, wl = tt>>5, lane = t&31;

    for(int i=t;i<4096;i+=512){ S.Wk00[i]=gWk00[i]; S.Wv00[i]=gWv00[i]; S.Wo0[i]=gWo0[i]; }
    for(int i=t;i<1024;i+=512){
        int ec=i>>6, c=i&63;
        S.Wk01t[i]=gWk01[c*16+ec]; S.Wv01t[i]=gWv01[c*16+ec];
        S.Wk10[i]=gWk10[i]; S.Wv10[i]=gWv10[i]; S.Rw20[i]=gRw20[i];
    }
    for(int i=t;i<256;i+=512){
        int ec=i>>4, c=i&15; int src=c*16+ec;
        S.Wk11t[i]=gWk11[src]; S.Wk11rt[i]=gWk11r[src];
        S.Wv11t[i]=gWv11[src]; S.Wv11rt[i]=gWv11r[src];
        S.Rw21t[i]=gRw21[src]; S.Wo1[i]=gWo1[i];
    }
    if(t<16){ S.Rw1[t]=gRw1[t]; S.Rb1[t]=gRb1[t]; }
    __syncthreads();

    // planar permutation targets for h1 gather
    int c1 = lane/3, m1 = lane - c1*3;  int p1 = m1*16 + c1;
    int idx2 = 32+lane; int c2i = idx2/3, m2 = idx2 - c2i*3; int p2 = m2*16 + c2i;

    for(int nb=blockIdx.x; nb<NODES/4; nb+=gridDim.x){
        int node = nb*4 + slot;
        if(tt<D0)           S.q0s[slot][tt]    = s_q0[node*D0+tt];
        else if(tt<D0+D13)  S.q1s[slot][tt-D0] = s_q1[node*D13+(tt-D0)];
        if(tt>=125)         S.ci[slot][tt-125] = coords[node*3+(tt-125)];
        __syncthreads();
        int bi = node >> 12;
        float ci0=S.ci[slot][0], ci1=S.ci[slot][1], ci2=S.ci[slot][2];

        // ---- pass A1: batched gather (planar h1) ----
        int rows[8];
        float hxr[8], hyr[8], hzr[8], ddr[8];
        #pragma unroll
        for(int e8=0;e8<8;e8++) rows[e8] = bi*NN + nbr[node*KK + wl*8 + e8];
        #pragma unroll
        for(int e8=0;e8<8;e8++){
            int row = rows[e8];
            S.h0g[slot][wl][e8][lane]    = s_g0[row*D0+lane];
            S.h0g[slot][wl][e8][lane+32] = s_g0[row*D0+32+lane];
            S.h1g[slot][wl][e8][p1]      = s_g1[row*D13+lane];
            if(lane<16) S.h1g[slot][wl][e8][p2] = s_g1[row*D13+32+lane];
            float rx = coords[row*3+0]-ci0;
            float ry = coords[row*3+1]-ci1;
            float rz = coords[row*3+2]-ci2;
            float dist = sqrtf(rx*rx+ry*ry+rz*rz);
            float inv = 1.0f/(dist+EPSF);
            hxr[e8]=rx*inv; hyr[e8]=ry*inv; hzr[e8]=rz*inv; ddr[e8]=dist;
        }
        __syncwarp();
        // ---- pass A2: geometry products (planar h1) ----
        #pragma unroll
        for(int e8=0;e8<8;e8++){
            if(lane==0){ S.rh4[slot][wl][e8][0]=hxr[e8]; S.rh4[slot][wl][e8][1]=hyr[e8];
                         S.rh4[slot][wl][e8][2]=hzr[e8]; S.rh4[slot][wl][e8][3]=ddr[e8]; }
            if(lane<16){
                const float* hp = S.h1g[slot][wl][e8];
                S.dot1g[slot][wl][e8][lane] = hp[lane]*hxr[e8] + hp[16+lane]*hyr[e8] + hp[32+lane]*hzr[e8];
                S.rhg[slot][wl][e8][lane] = gelu_f(ddr[e8]*S.Rw1[lane] + S.Rb1[lane]);
            }
        }
        __syncwarp();

        // ---- pass K1V1: packed u64 dataflow (writes logits "=") ----
        {
            int ec = lane&15; bool isK = lane<16;
            const float* W01t  = isK ? S.Wk01t  : S.Wv01t;
            const float* W11t  = isK ? S.Wk11t  : S.Wv11t;
            const float* W11rt = isK ? S.Wk11rt : S.Wv11rt;
            u64 a2[8];
            #pragma unroll
            for(int e=0;e<8;e++) a2[e]=0;
            #pragma unroll 8
            for(int c=0;c<D0;c+=2){
                u64 w2 = *reinterpret_cast<const u64*>(&W01t[ec*64+c]);
                #pragma unroll
                for(int e=0;e<8;e++)
                    fma2(a2[e], *reinterpret_cast<const u64*>(&S.h0g[slot][wl][e][c]), w2);
            }
            #pragma unroll
            for(int c=0;c<D1;c+=2){
                u64 w2 = *reinterpret_cast<const u64*>(&W11rt[ec*16+c]);
                #pragma unroll
                for(int e=0;e<8;e++)
                    fma2(a2[e], *reinterpret_cast<const u64*>(&S.dot1g[slot][wl][e][c]), w2);
            }
            float sr[8];
            #pragma unroll
            for(int e=0;e<8;e++){ float lo,hi; upk2(lo,hi,a2[e]); sr[e]=lo+hi; }
            #pragma unroll
            for(int e=0;e<8;e++) a2[e]=0;
            #pragma unroll
            for(int c=0;c<RH;c+=2){
                u64 w2 = *reinterpret_cast<const u64*>(&S.Rw21t[ec*16+c]);
                #pragma unroll
                for(int e=0;e<8;e++)
                    fma2(a2[e], *reinterpret_cast<const u64*>(&S.rhg[slot][wl][e][c]), w2);
            }
            float r1a[8];
            #pragma unroll
            for(int e=0;e<8;e++){ float lo,hi; upk2(lo,hi,a2[e]); r1a[e]=lo+hi; }
            float smv[3][8];
            #pragma unroll
            for(int m=0;m<3;m++){
                #pragma unroll
                for(int e=0;e<8;e++) a2[e]=0;
                #pragma unroll
                for(int c=0;c<D1;c+=2){
                    u64 w2 = *reinterpret_cast<const u64*>(&W11t[ec*16+c]);
                    #pragma unroll
                    for(int e=0;e<8;e++)
                        fma2(a2[e], *reinterpret_cast<const u64*>(&S.h1g[slot][wl][e][m*16+c]), w2);
                }
                #pragma unroll
                for(int e=0;e<8;e++){ float lo,hi; upk2(lo,hi,a2[e]); smv[m][e]=lo+hi; }
            }
            float q1x=S.q1s[slot][ec*3+0], q1y=S.q1s[slot][ec*3+1], q1z=S.q1s[slot][ec*3+2];
            #pragma unroll
            for(int e=0;e<8;e++){
                float hx=S.rh4[slot][wl][e][0], hy=S.rh4[slot][wl][e][1], hz=S.rh4[slot][wl][e][2];
                float kx=(sr[e]*hx+smv[0][e])*r1a[e];
                float ky=(sr[e]*hy+smv[1][e])*r1a[e];
                float kz=(sr[e]*hz+smv[2][e])*r1a[e];
                int eg = wl*8+e;
                float p = q1x*kx + q1y*ky + q1z*kz;
                p += __shfl_xor_sync(0xffffffffu,p,1);
                p += __shfl_xor_sync(0xffffffffu,p,2);
                if(isK){
                    if((lane&3)==0) S.logits[slot][ec>>2][eg] = p;
                } else {
                    S.v1s[slot][eg*D13+ec*3+0]=kx;
                    S.v1s[slot][eg*D13+ec*3+1]=ky;
                    S.v1s[slot][eg*D13+ec*3+2]=kz;
                }
            }
            __syncwarp();
        }

        // ---- pass B: k0/v0/r0 FFMA2 GEMM + logits (accumulates "+=") ----
        {
            float q0a = S.q0s[slot][2*lane], q0b = S.q0s[slot][2*lane+1];
            u64 ak[8], av[8];
            #pragma unroll
            for(int e=0;e<8;e++){ ak[e]=0; av[e]=0; }
            #pragma unroll 2
            for(int c=0;c<D0;c++){
                u64 wk = *reinterpret_cast<const u64*>(&S.Wk00[c*D0+2*lane]);
                u64 wv = *reinterpret_cast<const u64*>(&S.Wv00[c*D0+2*lane]);
                #pragma unroll
                for(int e=0;e<8;e++){
                    u64 h = dup2(S.h0g[slot][wl][e][c]);
                    fma2(ak[e],h,wk); fma2(av[e],h,wv);
                }
            }
            #pragma unroll
            for(int c=0;c<D1;c++){
                u64 wk = *reinterpret_cast<const u64*>(&S.Wk10[c*D0+2*lane]);
                u64 wv = *reinterpret_cast<const u64*>(&S.Wv10[c*D0+2*lane]);
                #pragma unroll
                for(int e=0;e<8;e++){
                    u64 d = dup2(S.dot1g[slot][wl][e][c]);
                    fma2(ak[e],d,wk); fma2(av[e],d,wv);
                }
            }
            u64 ar[8];
            #pragma unroll
            for(int e=0;e<8;e++) ar[e]=0;
            #pragma unroll
            for(int c=0;c<RH;c++){
                u64 wr = *reinterpret_cast<const u64*>(&S.Rw20[c*D0+2*lane]);
                #pragma unroll
                for(int e=0;e<8;e++) fma2(ar[e], dup2(S.rhg[slot][wl][e][c]), wr);
            }
            #pragma unroll
            for(int e=0;e<8;e++){
                float klo,khi,vlo,vhi,rlo,rhi;
                upk2(klo,khi,ak[e]); upk2(vlo,vhi,av[e]); upk2(rlo,rhi,ar[e]);
                klo*=rlo; khi*=rhi; vlo*=rlo; vhi*=rhi;
                int eg = wl*8+e;
                *reinterpret_cast<u64*>(&S.v0s[slot][eg*D0+2*lane]) = pk2(vlo,vhi);
                float p = q0a*klo + q0b*khi;
                p += __shfl_xor_sync(0xffffffffu,p,1);
                p += __shfl_xor_sync(0xffffffffu,p,2);
                p += __shfl_xor_sync(0xffffffffu,p,4);
                if((lane&7)==0) S.logits[slot][lane>>3][eg] += p;
            }
        }
        __syncthreads();

        // ---- softmax ----
        {
            int h=wl, e=lane;
            float x=S.logits[slot][h][e]*SCALE;
            float m=x;
            #pragma unroll
            for(int o=16;o>0;o>>=1) m=fmaxf(m,__shfl_xor_sync(0xffffffffu,m,o));
            float ex=__expf(x-m);
            float ssum=ex;
            #pragma unroll
            for(int o=16;o>0;o>>=1) ssum+=__shfl_xor_sync(0xffffffffu,ssum,o);
            S.a_s[slot][h][e]=ex/ssum;
        }
        __syncthreads();
        if(tt<D0){
            int h=tt>>4;
            float acc=0.f;
            #pragma unroll 8
            for(int e=0;e<KK;e++) acc += S.a_s[slot][h][e]*S.v0s[slot][e*D0+tt];
            S.o0s[slot][tt]=acc;
        } else if(tt<D0+D13){
            int idx=tt-D0;
            int h=(idx/3)>>2;
            float acc=0.f;
            #pragma unroll 8
            for(int e=0;e<KK;e++) acc += S.a_s[slot][h][e]*S.v1s[slot][e*D13+idx];
            S.o1s[slot][idx]=acc;
        }
        __syncthreads();
        if(tt<D0){
            float acc=s_f0[node*D0+tt];
            #pragma unroll 8
            for(int c=0;c<D0;c++) acc += S.o0s[slot][c]*S.Wo0[c*D0+tt];
            s_f0[node*D0+tt]=acc;
        } else if(tt<D0+D13){
            int idx=tt-D0; int ec=idx/3, m=idx-ec*3;
            float acc=s_f1[node*D13+idx];
            #pragma unroll
            for(int c=0;c<D1;c++) acc += S.o1s[slot][c*3+m]*S.Wo1[c*D1+ec];
            s_f1[node*D13+idx]=acc;
        }
        __syncthreads();
    }
}

// ---------------- FFN (proven R6 version) ----------------
struct FfnSmem {
    float F0w1[D0*256];
    float F0w2[256*D0];
    float F1w1[D1*64];
    float F1w2[64*D1];
    float g0s[4][D0], g1s[4][D13];
    float hmid[4][256];
    float u1[4][192];
    float sred[4][4][4];
    float red2[4][256];
};

__global__ void __launch_bounds__(512) ffn_kernel(
    const float* __restrict__ F0w1, const float* __restrict__ F0w2,
    const float* __restrict__ F1w1, const float* __restrict__ F1w2)
{
    extern __shared__ float ffn_smem_raw[];
    FfnSmem& S = *reinterpret_cast<FfnSmem*>(ffn_smem_raw);
    int t = threadIdx.x, slot = t>>7, tt = t&127, wi = tt>>5;
    for(int i=t;i<D0*256;i+=512){ S.F0w1[i]=F0w1[i]; S.F0w2[i]=F0w2[i]; }
    for(int i=t;i<D1*64;i+=512){ S.F1w1[i]=F1w1[i]; S.F1w2[i]=F1w2[i]; }
    __syncthreads();
    for(int base=blockIdx.x*4; base<NODES; base+=gridDim.x*4){
        int node = base + slot;
        float x = (tt<D0)? s_f0[node*D0+tt] : 0.f;
        float y = (tt<D13)? s_f1[node*D13+tt] : 0.f;
        float p0 = wred(x), p1 = wred(x*x), p2 = wred(y*y);
        if((t&31)==0){ S.sred[slot][wi][0]=p0; S.sred[slot][wi][1]=p1; S.sred[slot][wi][2]=p2; }
        __syncthreads();
        float sx  = S.sred[slot][0][0]+S.sred[slot][1][0]+S.sred[slot][2][0]+S.sred[slot][3][0];
        float sx2 = S.sred[slot][0][1]+S.sred[slot][1][1]+S.sred[slot][2][1]+S.sred[slot][3][1];
        float sy2 = S.sred[slot][0][2]+S.sred[slot][1][2]+S.sred[slot][2][2]+S.sred[slot][3][2];
        float mean = sx*(1.f/64.f);
        float var  = sx2*(1.f/64.f) - mean*mean;
        if(tt<D0) S.g0s[slot][tt]=(x-mean)*rsqrtf(var+EPSF);
        float rms = rsqrtf(sy2*(1.f/16.f)+EPSF);
        if(tt<D13) S.g1s[slot][tt]=y*rms;
        __syncthreads();
        {
            u64 a0=0, a1=0;
            #pragma unroll 8
            for(int c=0;c<D0;c+=2){
                fma2(a0, dup2(S.g0s[slot][c]),
                     *reinterpret_cast<const u64*>(&S.F0w1[c*256+2*tt]));
                fma2(a1, dup2(S.g0s[slot][c+1]),
                     *reinterpret_cast<const u64*>(&S.F0w1[(c+1)*256+2*tt]));
            }
            float lo0,hi0,lo1,hi1; upk2(lo0,hi0,a0); upk2(lo1,hi1,a1);
            S.hmid[slot][2*tt]=gelu_f(lo0+lo1); S.hmid[slot][2*tt+1]=gelu_f(hi0+hi1);
        }
        for(int idx=tt;idx<192;idx+=128){
            int ee=idx/3, m=idx-ee*3;
            float a=0.f;
            #pragma unroll
            for(int c=0;c<D1;c++) a += S.g1s[slot][c*3+m]*S.F1w1[c*64+ee];
            S.u1[slot][idx]=a;
        }
        __syncthreads();
        {
            int c2 = tt&31, jq = tt>>5;
            u64 a0=0, a1=0;
            #pragma unroll 8
            for(int j=0;j<64;j+=2){
                int jj = jq*64+j;
                fma2(a0, dup2(S.hmid[slot][jj]),
                     *reinterpret_cast<const u64*>(&S.F0w2[jj*D0+2*c2]));
                fma2(a1, dup2(S.hmid[slot][jj+1]),
                     *reinterpret_cast<const u64*>(&S.F0w2[(jj+1)*D0+2*c2]));
            }
            float lo0,hi0,lo1,hi1; upk2(lo0,hi0,a0); upk2(lo1,hi1,a1);
            S.red2[slot][jq*64+2*c2]=lo0+lo1; S.red2[slot][jq*64+2*c2+1]=hi0+hi1;
        }
        if(tt<64){
            float a0=S.u1[slot][tt*3],a1=S.u1[slot][tt*3+1],a2=S.u1[slot][tt*3+2];
            float nrm=sqrtf(a0*a0+a1*a1+a2*a2);
            float g=1.f/(1.f+__expf(-nrm));
            S.u1[slot][tt*3]=a0*g; S.u1[slot][tt*3+1]=a1*g; S.u1[slot][tt*3+2]=a2*g;
        }
        __syncthreads();
        if(tt<D0){
            float acc = s_f0[node*D0+tt] + S.red2[slot][tt] + S.red2[slot][64+tt]
                      + S.red2[slot][128+tt] + S.red2[slot][192+tt];
            s_f0[node*D0+tt]=acc;
        } else if(tt<D0+D13){
            int idx=tt-D0; int c=idx/3, m=idx-c*3;
            float acc=s_f1[node*D13+idx];
            #pragma unroll
            for(int ee=0;ee<64;ee++) acc += S.u1[slot][ee*3+m]*S.F1w2[ee*D1+c];
            s_f1[node*D13+idx]=acc;
        }
        __syncthreads();
    }
}

__global__ void out_kernel(float* __restrict__ out){
    int i = blockIdx.x*blockDim.x + threadIdx.x;
    if(i < NODES*112){
        int node=i/112, c=i-node*112;
        out[i] = (c<D0)? s_f0[node*D0+c] : s_f1[node*D13+(c-D0)];
    }
}

extern "C" void kernel_launch(void* const* d_in, const int* in_sizes, int n_in,
                              void* d_out, int out_size){
    const float* f0    =(const float*)d_in[0];
    const float* f1    =(const float*)d_in[1];
    const float* coords=(const float*)d_in[2];
    const int*   nbr   =(const int*)  d_in[3];
    const float* Wq0   =(const float*)d_in[4];
    const float* Wq1   =(const float*)d_in[5];
    const float* Wk00  =(const float*)d_in[6];
    const float* Wk10  =(const float*)d_in[7];
    const float* Wk01  =(const float*)d_in[8];
    const float* Wk11  =(const float*)d_in[9];
    const float* Wk11r =(const float*)d_in[10];
    const float* Wv00  =(const float*)d_in[11];
    const float* Wv10  =(const float*)d_in[12];
    const float* Wv01  =(const float*)d_in[13];
    const float* Wv11  =(const float*)d_in[14];
    const float* Wv11r =(const float*)d_in[15];
    const float* Rw1   =(const float*)d_in[16];
    const float* Rb1   =(const float*)d_in[17];
    const float* Rw20  =(const float*)d_in[18];
    const float* Rw21  =(const float*)d_in[19];
    const float* Wo0   =(const float*)d_in[20];
    const float* Wo1   =(const float*)d_in[21];
    const float* F0w1  =(const float*)d_in[22];
    const float* F0w2  =(const float*)d_in[23];
    const float* F1w1  =(const float*)d_in[24];
    const float* F1w2  =(const float*)d_in[25];

    cudaFuncSetAttribute(attn_kernel, cudaFuncAttributeMaxDynamicSharedMemorySize, (int)sizeof(AttnSmem));
    cudaFuncSetAttribute(ffn_kernel,  cudaFuncAttributeMaxDynamicSharedMemorySize, (int)sizeof(FfnSmem));

    init_kernel<<<(NODES*D0+255)/256,256>>>(f0,f1);
    for(int l=0;l<2;l++){
        prenorm_q_kernel<<<NODES/8,256>>>(Wq0 + l*D0*D0, Wq1 + l*D1*D1);
        attn_kernel<<<148,512,sizeof(AttnSmem)>>>(coords, nbr,
            Wk00 + l*D0*D0, Wk10 + l*D1*D0, Wk01 + l*D0*D1, Wk11 + l*D1*D1, Wk11r + l*D1*D1,
            Wv00 + l*D0*D0, Wv10 + l*D1*D0, Wv01 + l*D0*D1, Wv11 + l*D1*D1, Wv11r + l*D1*D1,
            Rw1 + l*RH, Rb1 + l*RH, Rw20 + l*RH*D0, Rw21 + l*RH*D1,
            Wo0 + l*D0*D0, Wo1 + l*D1*D1);
        ffn_kernel<<<148,512,sizeof(FfnSmem)>>>(F0w1 + l*D0*256, F0w2 + l*256*D0,
                                                F1w1 + l*D1*64,  F1w2 + l*64*D1);
    }
    out_kernel<<<(NODES*112+255)/256,256>>>((float*)d_out);
}

// round 17
// speedup vs baseline: 1.2188x; 1.2188x over previous
#include <cuda_runtime.h>
#include <math.h>

#define BB 2
#define NN 4096
#define NODES (BB*NN)
#define KK 32
#define D0 64
#define D1 16
#define D13 48
#define RH 16
#define EPSF 1e-6f
#define SCALE 0.1889822365046136f

typedef unsigned long long u64;

__device__ float s_f0[NODES*D0];
__device__ float s_f1[NODES*D13];
__device__ float s_g0[NODES*D0];
__device__ float s_g1[NODES*D13];
__device__ float s_q0[NODES*D0];
__device__ float s_q1[NODES*D13];

__device__ __forceinline__ float gelu_f(float x){
    float x3 = x*x*x;
    return 0.5f*x*(1.0f + tanhf(0.7978845608028654f*(x + 0.044715f*x3)));
}
__device__ __forceinline__ u64 pk2(float lo, float hi){
    u64 r; asm("mov.b64 %0,{%1,%2};" : "=l"(r) : "f"(lo), "f"(hi)); return r;
}
__device__ __forceinline__ u64 dup2(float x){ return pk2(x,x); }
__device__ __forceinline__ void upk2(float&lo, float&hi, u64 v){
    asm("mov.b64 {%0,%1},%2;" : "=f"(lo), "=f"(hi) : "l"(v));
}
__device__ __forceinline__ void fma2(u64 &d, u64 a, u64 b){
    asm("fma.rn.f32x2 %0,%1,%2,%0;" : "+l"(d) : "l"(a), "l"(b));
}
__device__ __forceinline__ u64 mul2(u64 a, u64 b){
    u64 d; asm("mul.rn.f32x2 %0,%1,%2;" : "=l"(d) : "l"(a), "l"(b)); return d;
}
__device__ __forceinline__ u64 add2(u64 a, u64 b){
    u64 d; asm("add.rn.f32x2 %0,%1,%2;" : "=l"(d) : "l"(a), "l"(b)); return d;
}
__device__ __forceinline__ float wred(float v){
    #pragma unroll
    for(int o=16;o>0;o>>=1) v += __shfl_xor_sync(0xffffffffu, v, o);
    return v;
}

__global__ void init_kernel(const float* __restrict__ f0, const float* __restrict__ f1){
    int i = blockIdx.x*blockDim.x + threadIdx.x;
    if(i < NODES*D0)  s_f0[i] = f0[i];
    if(i < NODES*D13) s_f1[i] = f1[i];
}

// ---------------- prenorm + Q (warp per node) ----------------
__global__ void __launch_bounds__(256) prenorm_q_kernel(
    const float* __restrict__ Wq0, const float* __restrict__ Wq1)
{
    __shared__ float Wq0s[D0*D0];
    __shared__ float Wq1s[D1*D1];
    __shared__ float g1tmp[8][49];
    int t = threadIdx.x, w = t>>5, lane = t&31;
    for(int i=t;i<D0*D0;i+=256) Wq0s[i]=Wq0[i];
    for(int i=t;i<D1*D1;i+=256) Wq1s[i]=Wq1[i];
    __syncthreads();
    int nd = blockIdx.x*8 + w;
    if(nd >= NODES) return;
    float x0 = s_f0[nd*D0+lane], x1 = s_f0[nd*D0+32+lane];
    float mean = wred(x0+x1)*(1.0f/64.0f);
    float d0_ = x0-mean, d1_ = x1-mean;
    float var = wred(d0_*d0_ + d1_*d1_)*(1.0f/64.0f);
    float rs = rsqrtf(var+EPSF);
    float g0a = d0_*rs, g0b = d1_*rs;
    s_g0[nd*D0+lane]=g0a; s_g0[nd*D0+32+lane]=g0b;
    float y0 = s_f1[nd*D13+lane];
    float y1 = (lane<16)? s_f1[nd*D13+32+lane] : 0.0f;
    float rms = rsqrtf(wred(y0*y0+y1*y1)*(1.0f/16.0f)+EPSF);
    float g1a = y0*rms, g1b = y1*rms;
    s_g1[nd*D13+lane]=g1a;
    if(lane<16) s_g1[nd*D13+32+lane]=g1b;
    g1tmp[w][lane]=g1a;
    if(lane<16) g1tmp[w][32+lane]=g1b;
    __syncwarp();
    u64 acc = 0;
    #pragma unroll 8
    for(int c=0;c<D0;c++){
        float xc = (c<32)? __shfl_sync(0xffffffffu,g0a,c) : __shfl_sync(0xffffffffu,g0b,c-32);
        u64 wp = *reinterpret_cast<const u64*>(&Wq0s[c*D0 + 2*lane]);
        fma2(acc, dup2(xc), wp);
    }
    float qlo,qhi; upk2(qlo,qhi,acc);
    s_q0[nd*D0+2*lane]=qlo; s_q0[nd*D0+2*lane+1]=qhi;
    if(lane<16){
        float a0=0.f,a1=0.f,a2=0.f;
        #pragma unroll
        for(int c=0;c<D1;c++){
            float wv = Wq1s[c*D1+lane];
            a0 += g1tmp[w][c*3+0]*wv;
            a1 += g1tmp[w][c*3+1]*wv;
            a2 += g1tmp[w][c*3+2]*wv;
        }
        s_q1[nd*D13+lane*3+0]=a0;
        s_q1[nd*D13+lane*3+1]=a1;
        s_q1[nd*D13+lane*3+2]=a2;
    }
}

// ---------------- attention: 4 nodes per 512-thread CTA ----------------
// h0/dot1/rh stored transposed [c][e] with stride 10 for edge-packed FFMA2.
struct AttnSmem {
    float Wk00[4096], Wv00[4096], Wo0[4096];
    float Wk10[1024], Wv10[1024], Rw20[1024];
    float Wk01[1024], Wv01[1024];
    float Wk11[256], Wk11r[256], Wv11[256], Wv11r[256], Rw21[256], Wo1[256];
    float Rw1[16], Rb1[16];
    float v0s[4][KK*D0];
    float v1s[4][KK*D13];
    float h0t[4][4][640];     // [slot][warp][c*10+e], c<64, e<8
    float h1g[4][4][8][50];   // original interleaved [e][c*3+m]
    float dot1t[4][4][160];   // [c*10+e], c<16
    float rhgt[4][4][160];    // [c*10+e], c<16
    float rh4[4][4][8][4];
    float logits[4][4][33];
    float a_s[4][4][33];
    float q0s[4][D0], q1s[4][D13], o0s[4][D0], o1s[4][D13];
    float ci[4][4];
};

__global__ void __launch_bounds__(512) attn_kernel(
    const float* __restrict__ coords, const int* __restrict__ nbr,
    const float* __restrict__ gWk00, const float* __restrict__ gWk10,
    const float* __restrict__ gWk01, const float* __restrict__ gWk11,
    const float* __restrict__ gWk11r,
    const float* __restrict__ gWv00, const float* __restrict__ gWv10,
    const float* __restrict__ gWv01, const float* __restrict__ gWv11,
    const float* __restrict__ gWv11r,
    const float* __restrict__ gRw1, const float* __restrict__ gRb1,
    const float* __restrict__ gRw20, const float* __restrict__ gRw21,
    const float* __restrict__ gWo0, const float* __restrict__ gWo1)
{
    extern __shared__ float smem_raw[];
    AttnSmem& S = *reinterpret_cast<AttnSmem*>(smem_raw);
    int t = threadIdx.x, slot = t>>7, tt = t&127, wl = tt>>5, lane = t&31;

    for(int i=t;i<4096;i+=512){ S.Wk00[i]=gWk00[i]; S.Wv00[i]=gWv00[i]; S.Wo0[i]=gWo0[i]; }
    for(int i=t;i<1024;i+=512){ S.Wk10[i]=gWk10[i]; S.Wv10[i]=gWv10[i]; S.Rw20[i]=gRw20[i];
                                S.Wk01[i]=gWk01[i]; S.Wv01[i]=gWv01[i]; }
    for(int i=t;i<256;i+=512){ S.Wk11[i]=gWk11[i]; S.Wk11r[i]=gWk11r[i];
                               S.Wv11[i]=gWv11[i]; S.Wv11r[i]=gWv11r[i];
                               S.Rw21[i]=gRw21[i]; S.Wo1[i]=gWo1[i]; }
    if(t<16){ S.Rw1[t]=gRw1[t]; S.Rb1[t]=gRb1[t]; }
    __syncthreads();

    for(int nb=blockIdx.x; nb<NODES/4; nb+=gridDim.x){
        int node = nb*4 + slot;
        if(tt<D0)           S.q0s[slot][tt]    = s_q0[node*D0+tt];
        else if(tt<D0+D13)  S.q1s[slot][tt-D0] = s_q1[node*D13+(tt-D0)];
        if(tt>=125)         S.ci[slot][tt-125] = coords[node*3+(tt-125)];
        __syncthreads();
        int bi = node >> 12;
        float ci0=S.ci[slot][0], ci1=S.ci[slot][1], ci2=S.ci[slot][2];
        float* h0p = S.h0t[slot][wl];
        float* d1p = S.dot1t[slot][wl];
        float* rhp = S.rhgt[slot][wl];

        // ---- pass A1: batched gather (h0 transposed) ----
        int rows[8];
        float hxr[8], hyr[8], hzr[8], ddr[8];
        #pragma unroll
        for(int e8=0;e8<8;e8++) rows[e8] = bi*NN + nbr[node*KK + wl*8 + e8];
        #pragma unroll
        for(int e8=0;e8<8;e8++){
            int row = rows[e8];
            h0p[lane*10+e8]      = s_g0[row*D0+lane];
            h0p[(32+lane)*10+e8] = s_g0[row*D0+32+lane];
            S.h1g[slot][wl][e8][lane]    = s_g1[row*D13+lane];
            if(lane<16) S.h1g[slot][wl][e8][32+lane] = s_g1[row*D13+32+lane];
            float rx = coords[row*3+0]-ci0;
            float ry = coords[row*3+1]-ci1;
            float rz = coords[row*3+2]-ci2;
            float dist = sqrtf(rx*rx+ry*ry+rz*rz);
            float inv = 1.0f/(dist+EPSF);
            hxr[e8]=rx*inv; hyr[e8]=ry*inv; hzr[e8]=rz*inv; ddr[e8]=dist;
        }
        __syncwarp();
        // ---- pass A2: geometry products (writes transposed dot1/rh) ----
        #pragma unroll
        for(int e8=0;e8<8;e8++){
            if(lane==0){ S.rh4[slot][wl][e8][0]=hxr[e8]; S.rh4[slot][wl][e8][1]=hyr[e8];
                         S.rh4[slot][wl][e8][2]=hzr[e8]; S.rh4[slot][wl][e8][3]=ddr[e8]; }
            if(lane<16){
                d1p[lane*10+e8] = S.h1g[slot][wl][e8][lane*3+0]*hxr[e8]
                                + S.h1g[slot][wl][e8][lane*3+1]*hyr[e8]
                                + S.h1g[slot][wl][e8][lane*3+2]*hzr[e8];
                rhp[lane*10+e8] = gelu_f(ddr[e8]*S.Rw1[lane] + S.Rb1[lane]);
            }
        }
        __syncwarp();

        // ---- pass K1V1 (edge-packed sr/r1; scalar sm) ----
        {
            int ec = lane&15; bool isK = lane<16;
            const float* W01  = isK ? S.Wk01  : S.Wv01;
            const float* W11  = isK ? S.Wk11  : S.Wv11;
            const float* W11r = isK ? S.Wk11r : S.Wv11r;
            u64 srp[4] = {0,0,0,0};
            #pragma unroll 8
            for(int c=0;c<D0;c++){
                u64 wd = dup2(W01[c*D1+ec]);
                #pragma unroll
                for(int p=0;p<4;p++)
                    fma2(srp[p], *reinterpret_cast<const u64*>(&h0p[c*10+2*p]), wd);
            }
            #pragma unroll
            for(int c=0;c<D1;c++){
                u64 wd = dup2(W11r[c*D1+ec]);
                #pragma unroll
                for(int p=0;p<4;p++)
                    fma2(srp[p], *reinterpret_cast<const u64*>(&d1p[c*10+2*p]), wd);
            }
            float sr[8];
            #pragma unroll
            for(int p=0;p<4;p++) upk2(sr[2*p],sr[2*p+1],srp[p]);
            float sm0[8], sm1[8], sm2[8];
            #pragma unroll
            for(int e=0;e<8;e++){ sm0[e]=0.f; sm1[e]=0.f; sm2[e]=0.f; }
            #pragma unroll
            for(int c=0;c<D1;c++){
                float wv = W11[c*D1+ec];
                #pragma unroll
                for(int e=0;e<8;e++){
                    sm0[e] += S.h1g[slot][wl][e][c*3+0]*wv;
                    sm1[e] += S.h1g[slot][wl][e][c*3+1]*wv;
                    sm2[e] += S.h1g[slot][wl][e][c*3+2]*wv;
                }
            }
            u64 r1p[4] = {0,0,0,0};
            #pragma unroll
            for(int c=0;c<RH;c++){
                u64 wd = dup2(S.Rw21[c*D1+ec]);
                #pragma unroll
                for(int p=0;p<4;p++)
                    fma2(r1p[p], *reinterpret_cast<const u64*>(&rhp[c*10+2*p]), wd);
            }
            float r1a[8];
            #pragma unroll
            for(int p=0;p<4;p++) upk2(r1a[2*p],r1a[2*p+1],r1p[p]);
            float q1x=S.q1s[slot][ec*3+0], q1y=S.q1s[slot][ec*3+1], q1z=S.q1s[slot][ec*3+2];
            #pragma unroll
            for(int e=0;e<8;e++){
                float hx=S.rh4[slot][wl][e][0], hy=S.rh4[slot][wl][e][1], hz=S.rh4[slot][wl][e][2];
                float kx=(sr[e]*hx+sm0[e])*r1a[e];
                float ky=(sr[e]*hy+sm1[e])*r1a[e];
                float kz=(sr[e]*hz+sm2[e])*r1a[e];
                int eg = wl*8+e;
                float p = q1x*kx + q1y*ky + q1z*kz;
                p += __shfl_xor_sync(0xffffffffu,p,1);
                p += __shfl_xor_sync(0xffffffffu,p,2);
                if(isK){
                    if((lane&3)==0) S.logits[slot][ec>>2][eg] = p;
                } else {
                    S.v1s[slot][eg*D13+ec*3+0]=kx;
                    S.v1s[slot][eg*D13+ec*3+1]=ky;
                    S.v1s[slot][eg*D13+ec*3+2]=kz;
                }
            }
            __syncwarp();
        }

        // ---- pass B: k0/v0/r0 edge-packed FFMA2 GEMM + logits (+=) ----
        {
            float q0a = S.q0s[slot][2*lane], q0b = S.q0s[slot][2*lane+1];
            u64 ak0[4],ak1[4],av0[4],av1[4];
            #pragma unroll
            for(int p=0;p<4;p++){ ak0[p]=0; ak1[p]=0; av0[p]=0; av1[p]=0; }
            #pragma unroll 2
            for(int c=0;c<D0;c++){
                float wka,wkb,wva,wvb;
                upk2(wka,wkb,*reinterpret_cast<const u64*>(&S.Wk00[c*D0+2*lane]));
                upk2(wva,wvb,*reinterpret_cast<const u64*>(&S.Wv00[c*D0+2*lane]));
                u64 wka2=dup2(wka), wkb2=dup2(wkb), wva2=dup2(wva), wvb2=dup2(wvb);
                #pragma unroll
                for(int p=0;p<4;p++){
                    u64 hp = *reinterpret_cast<const u64*>(&h0p[c*10+2*p]);
                    fma2(ak0[p],hp,wka2); fma2(ak1[p],hp,wkb2);
                    fma2(av0[p],hp,wva2); fma2(av1[p],hp,wvb2);
                }
            }
            #pragma unroll
            for(int c=0;c<D1;c++){
                float wka,wkb,wva,wvb;
                upk2(wka,wkb,*reinterpret_cast<const u64*>(&S.Wk10[c*D0+2*lane]));
                upk2(wva,wvb,*reinterpret_cast<const u64*>(&S.Wv10[c*D0+2*lane]));
                u64 wka2=dup2(wka), wkb2=dup2(wkb), wva2=dup2(wva), wvb2=dup2(wvb);
                #pragma unroll
                for(int p=0;p<4;p++){
                    u64 dp = *reinterpret_cast<const u64*>(&d1p[c*10+2*p]);
                    fma2(ak0[p],dp,wka2); fma2(ak1[p],dp,wkb2);
                    fma2(av0[p],dp,wva2); fma2(av1[p],dp,wvb2);
                }
            }
            u64 ar0[4],ar1[4];
            #pragma unroll
            for(int p=0;p<4;p++){ ar0[p]=0; ar1[p]=0; }
            #pragma unroll
            for(int c=0;c<RH;c++){
                float wra,wrb;
                upk2(wra,wrb,*reinterpret_cast<const u64*>(&S.Rw20[c*D0+2*lane]));
                u64 wra2=dup2(wra), wrb2=dup2(wrb);
                #pragma unroll
                for(int p=0;p<4;p++){
                    u64 hp = *reinterpret_cast<const u64*>(&rhp[c*10+2*p]);
                    fma2(ar0[p],hp,wra2); fma2(ar1[p],hp,wrb2);
                }
            }
            #pragma unroll
            for(int p=0;p<4;p++){
                u64 k0 = mul2(ak0[p],ar0[p]);
                u64 k1 = mul2(ak1[p],ar1[p]);
                u64 v0 = mul2(av0[p],ar0[p]);
                u64 v1 = mul2(av1[p],ar1[p]);
                float v0a,v0b,v1a,v1b;
                upk2(v0a,v0b,v0); upk2(v1a,v1b,v1);
                int eg0 = wl*8+2*p, eg1 = eg0+1;
                *reinterpret_cast<u64*>(&S.v0s[slot][eg0*D0+2*lane]) = pk2(v0a,v1a);
                *reinterpret_cast<u64*>(&S.v0s[slot][eg1*D0+2*lane]) = pk2(v0b,v1b);
                u64 pp = 0;
                fma2(pp, dup2(q0a), k0);
                fma2(pp, dup2(q0b), k1);
                pp = add2(pp, __shfl_xor_sync(0xffffffffu, pp, 1));
                pp = add2(pp, __shfl_xor_sync(0xffffffffu, pp, 2));
                pp = add2(pp, __shfl_xor_sync(0xffffffffu, pp, 4));
                if((lane&7)==0){
                    float pl,ph; upk2(pl,ph,pp);
                    S.logits[slot][lane>>3][eg0] += pl;
                    S.logits[slot][lane>>3][eg1] += ph;
                }
            }
        }
        __syncthreads();

        // ---- softmax ----
        {
            int h=wl, e=lane;
            float x=S.logits[slot][h][e]*SCALE;
            float m=x;
            #pragma unroll
            for(int o=16;o>0;o>>=1) m=fmaxf(m,__shfl_xor_sync(0xffffffffu,m,o));
            float ex=__expf(x-m);
            float ssum=ex;
            #pragma unroll
            for(int o=16;o>0;o>>=1) ssum+=__shfl_xor_sync(0xffffffffu,ssum,o);
            S.a_s[slot][h][e]=ex/ssum;
        }
        __syncthreads();
        if(tt<D0){
            int h=tt>>4;
            float acc=0.f;
            #pragma unroll 8
            for(int e=0;e<KK;e++) acc += S.a_s[slot][h][e]*S.v0s[slot][e*D0+tt];
            S.o0s[slot][tt]=acc;
        } else if(tt<D0+D13){
            int idx=tt-D0;
            int h=(idx/3)>>2;
            float acc=0.f;
            #pragma unroll 8
            for(int e=0;e<KK;e++) acc += S.a_s[slot][h][e]*S.v1s[slot][e*D13+idx];
            S.o1s[slot][idx]=acc;
        }
        __syncthreads();
        if(tt<D0){
            float acc=s_f0[node*D0+tt];
            #pragma unroll 8
            for(int c=0;c<D0;c++) acc += S.o0s[slot][c]*S.Wo0[c*D0+tt];
            s_f0[node*D0+tt]=acc;
        } else if(tt<D0+D13){
            int idx=tt-D0; int ec=idx/3, m=idx-ec*3;
            float acc=s_f1[node*D13+idx];
            #pragma unroll
            for(int c=0;c<D1;c++) acc += S.o1s[slot][c*3+m]*S.Wo1[c*D1+ec];
            s_f1[node*D13+idx]=acc;
        }
        __syncthreads();
    }
}

// ---------------- FFN (proven version) ----------------
struct FfnSmem {
    float F0w1[D0*256];
    float F0w2[256*D0];
    float F1w1[D1*64];
    float F1w2[64*D1];
    float g0s[4][D0], g1s[4][D13];
    float hmid[4][256];
    float u1[4][192];
    float sred[4][4][4];
    float red2[4][256];
};

__global__ void __launch_bounds__(512) ffn_kernel(
    const float* __restrict__ F0w1, const float* __restrict__ F0w2,
    const float* __restrict__ F1w1, const float* __restrict__ F1w2)
{
    extern __shared__ float ffn_smem_raw[];
    FfnSmem& S = *reinterpret_cast<FfnSmem*>(ffn_smem_raw);
    int t = threadIdx.x, slot = t>>7, tt = t&127, wi = tt>>5;
    for(int i=t;i<D0*256;i+=512){ S.F0w1[i]=F0w1[i]; S.F0w2[i]=F0w2[i]; }
    for(int i=t;i<D1*64;i+=512){ S.F1w1[i]=F1w1[i]; S.F1w2[i]=F1w2[i]; }
    __syncthreads();
    for(int base=blockIdx.x*4; base<NODES; base+=gridDim.x*4){
        int node = base + slot;
        float x = (tt<D0)? s_f0[node*D0+tt] : 0.f;
        float y = (tt<D13)? s_f1[node*D13+tt] : 0.f;
        float p0 = wred(x), p1 = wred(x*x), p2 = wred(y*y);
        if((t&31)==0){ S.sred[slot][wi][0]=p0; S.sred[slot][wi][1]=p1; S.sred[slot][wi][2]=p2; }
        __syncthreads();
        float sx  = S.sred[slot][0][0]+S.sred[slot][1][0]+S.sred[slot][2][0]+S.sred[slot][3][0];
        float sx2 = S.sred[slot][0][1]+S.sred[slot][1][1]+S.sred[slot][2][1]+S.sred[slot][3][1];
        float sy2 = S.sred[slot][0][2]+S.sred[slot][1][2]+S.sred[slot][2][2]+S.sred[slot][3][2];
        float mean = sx*(1.f/64.f);
        float var  = sx2*(1.f/64.f) - mean*mean;
        if(tt<D0) S.g0s[slot][tt]=(x-mean)*rsqrtf(var+EPSF);
        float rms = rsqrtf(sy2*(1.f/16.f)+EPSF);
        if(tt<D13) S.g1s[slot][tt]=y*rms;
        __syncthreads();
        {
            u64 a0=0, a1=0;
            #pragma unroll 8
            for(int c=0;c<D0;c+=2){
                fma2(a0, dup2(S.g0s[slot][c]),
                     *reinterpret_cast<const u64*>(&S.F0w1[c*256+2*tt]));
                fma2(a1, dup2(S.g0s[slot][c+1]),
                     *reinterpret_cast<const u64*>(&S.F0w1[(c+1)*256+2*tt]));
            }
            float lo0,hi0,lo1,hi1; upk2(lo0,hi0,a0); upk2(lo1,hi1,a1);
            S.hmid[slot][2*tt]=gelu_f(lo0+lo1); S.hmid[slot][2*tt+1]=gelu_f(hi0+hi1);
        }
        for(int idx=tt;idx<192;idx+=128){
            int ee=idx/3, m=idx-ee*3;
            float a=0.f;
            #pragma unroll
            for(int c=0;c<D1;c++) a += S.g1s[slot][c*3+m]*S.F1w1[c*64+ee];
            S.u1[slot][idx]=a;
        }
        __syncthreads();
        {
            int c2 = tt&31, jq = tt>>5;
            u64 a0=0, a1=0;
            #pragma unroll 8
            for(int j=0;j<64;j+=2){
                int jj = jq*64+j;
                fma2(a0, dup2(S.hmid[slot][jj]),
                     *reinterpret_cast<const u64*>(&S.F0w2[jj*D0+2*c2]));
                fma2(a1, dup2(S.hmid[slot][jj+1]),
                     *reinterpret_cast<const u64*>(&S.F0w2[(jj+1)*D0+2*c2]));
            }
            float lo0,hi0,lo1,hi1; upk2(lo0,hi0,a0); upk2(lo1,hi1,a1);
            S.red2[slot][jq*64+2*c2]=lo0+lo1; S.red2[slot][jq*64+2*c2+1]=hi0+hi1;
        }
        if(tt<64){
            float a0=S.u1[slot][tt*3],a1=S.u1[slot][tt*3+1],a2=S.u1[slot][tt*3+2];
            float nrm=sqrtf(a0*a0+a1*a1+a2*a2);
            float g=1.f/(1.f+__expf(-nrm));
            S.u1[slot][tt*3]=a0*g; S.u1[slot][tt*3+1]=a1*g; S.u1[slot][tt*3+2]=a2*g;
        }
        __syncthreads();
        if(tt<D0){
            float acc = s_f0[node*D0+tt] + S.red2[slot][tt] + S.red2[slot][64+tt]
                      + S.red2[slot][128+tt] + S.red2[slot][192+tt];
            s_f0[node*D0+tt]=acc;
        } else if(tt<D0+D13){
            int idx=tt-D0; int c=idx/3, m=idx-c*3;
            float acc=s_f1[node*D13+idx];
            #pragma unroll
            for(int ee=0;ee<64;ee++) acc += S.u1[slot][ee*3+m]*S.F1w2[ee*D1+c];
            s_f1[node*D13+idx]=acc;
        }
        __syncthreads();
    }
}

__global__ void out_kernel(float* __restrict__ out){
    int i = blockIdx.x*blockDim.x + threadIdx.x;
    if(i < NODES*112){
        int node=i/112, c=i-node*112;
        out[i] = (c<D0)? s_f0[node*D0+c] : s_f1[node*D13+(c-D0)];
    }
}

extern "C" void kernel_launch(void* const* d_in, const int* in_sizes, int n_in,
                              void* d_out, int out_size){
    const float* f0    =(const float*)d_in[0];
    const float* f1    =(const float*)d_in[1];
    const float* coords=(const float*)d_in[2];
    const int*   nbr   =(const int*)  d_in[3];
    const float* Wq0   =(const float*)d_in[4];
    const float* Wq1   =(const float*)d_in[5];
    const float* Wk00  =(const float*)d_in[6];
    const float* Wk10  =(const float*)d_in[7];
    const float* Wk01  =(const float*)d_in[8];
    const float* Wk11  =(const float*)d_in[9];
    const float* Wk11r =(const float*)d_in[10];
    const float* Wv00  =(const float*)d_in[11];
    const float* Wv10  =(const float*)d_in[12];
    const float* Wv01  =(const float*)d_in[13];
    const float* Wv11  =(const float*)d_in[14];
    const float* Wv11r =(const float*)d_in[15];
    const float* Rw1   =(const float*)d_in[16];
    const float* Rb1   =(const float*)d_in[17];
    const float* Rw20  =(const float*)d_in[18];
    const float* Rw21  =(const float*)d_in[19];
    const float* Wo0   =(const float*)d_in[20];
    const float* Wo1   =(const float*)d_in[21];
    const float* F0w1  =(const float*)d_in[22];
    const float* F0w2  =(const float*)d_in[23];
    const float* F1w1  =(const float*)d_in[24];
    const float* F1w2  =(const float*)d_in[25];

    cudaFuncSetAttribute(attn_kernel, cudaFuncAttributeMaxDynamicSharedMemorySize, (int)sizeof(AttnSmem));
    cudaFuncSetAttribute(ffn_kernel,  cudaFuncAttributeMaxDynamicSharedMemorySize, (int)sizeof(FfnSmem));

    init_kernel<<<(NODES*D0+255)/256,256>>>(f0,f1);
    for(int l=0;l<2;l++){
        prenorm_q_kernel<<<NODES/8,256>>>(Wq0 + l*D0*D0, Wq1 + l*D1*D1);
        attn_kernel<<<148,512,sizeof(AttnSmem)>>>(coords, nbr,
            Wk00 + l*D0*D0, Wk10 + l*D1*D0, Wk01 + l*D0*D1, Wk11 + l*D1*D1, Wk11r + l*D1*D1,
            Wv00 + l*D0*D0, Wv10 + l*D1*D0, Wv01 + l*D0*D1, Wv11 + l*D1*D1, Wv11r + l*D1*D1,
            Rw1 + l*RH, Rb1 + l*RH, Rw20 + l*RH*D0, Rw21 + l*RH*D1,
            Wo0 + l*D0*D0, Wo1 + l*D1*D1);
        ffn_kernel<<<148,512,sizeof(FfnSmem)>>>(F0w1 + l*D0*256, F0w2 + l*256*D0,
                                                F1w1 + l*D1*64,  F1w2 + l*64*D1);
    }
    out_kernel<<<(NODES*112+255)/256,256>>>((float*)d_out);
}